// round 2
// baseline (speedup 1.0000x reference)
#include <cuda_runtime.h>
#include <math.h>

#define BB 4
#define NN 4096
#define KK 20
#define NPTS (BB*NN)            // 16384
#define EDG  (NPTS*KK)          // 327680
#define STATS_BLOCKS 512

#define FINF __int_as_float(0x7f800000)

// ---------------- scratch (device globals; no allocations allowed) ----------
__device__ float g_dist[(size_t)BB * NN * NN];   // 268 MB distance matrix (layer 1)
__device__ float g_d2[NPTS];
__device__ int   g_idx[NPTS * KK];
__device__ float g_u[NPTS * 256];
__device__ float g_v[NPTS * 256];
__device__ float g_h0[NPTS * 64];
__device__ float g_h1[NPTS * 256];
__device__ float g_Wd0[3 * 64];
__device__ float g_Wd1[64 * 256];
__device__ float g_part[STATS_BLOCKS * 2 * 256];
__device__ float g_scale[256];
__device__ float g_shift[256];
__device__ float g_gate[NPTS];
__device__ float g_alpha[NPTS];
__device__ float g_pool[32 * BB * 512];
__device__ float g_pooled[BB * 512];

static __device__ __forceinline__ float leaky(float v) { return v > 0.f ? v : 0.2f * v; }

// ---------------- weight prep: Wd = Wp - Wt ---------------------------------
__global__ void prep_k(const float* __restrict__ Wt0, const float* __restrict__ Wp0,
                       const float* __restrict__ Wt1, const float* __restrict__ Wp1) {
    int i = blockIdx.x * 256 + threadIdx.x;
    if (i < 192) g_Wd0[i] = Wp0[i] - Wt0[i];
    int j = i - 192;
    if (j >= 0 && j < 16384) g_Wd1[j] = Wp1[j] - Wt1[j];
}

// ---------------- squared norms ---------------------------------------------
__global__ void norms3_k(const float* __restrict__ x) {
    int r = blockIdx.x * blockDim.x + threadIdx.x;
    if (r >= NPTS) return;
    float a = x[r * 3], b = x[r * 3 + 1], c = x[r * 3 + 2];
    g_d2[r] = a * a + b * b + c * c;
}

__global__ void norms64_k() {
    int gt = blockIdx.x * blockDim.x + threadIdx.x;
    int r = gt >> 5, lane = gt & 31;
    if (r >= NPTS) return;
    const float* h = g_h0 + (size_t)r * 64;
    float a = h[lane], b = h[lane + 32];
    float s = a * a + b * b;
    #pragma unroll
    for (int o = 16; o; o >>= 1) s += __shfl_down_sync(0xffffffffu, s, o);
    if (lane == 0) g_d2[r] = s;
}

// ---------------- layer0 u/v (3->64, trivial) --------------------------------
__global__ void uv0_k(const float* __restrict__ x, const float* __restrict__ Wt0) {
    int gid = blockIdx.x * 256 + threadIdx.x;   // NPTS*64 total
    int r = gid >> 6, c = gid & 63;
    float x0 = x[r * 3], x1 = x[r * 3 + 1], x2 = x[r * 3 + 2];
    g_u[gid] = x0 * Wt0[c] + x1 * Wt0[64 + c] + x2 * Wt0[128 + c];
    g_v[gid] = x0 * g_Wd0[c] + x1 * g_Wd0[64 + c] + x2 * g_Wd0[128 + c];
}

// ---------------- fused 16-row (64->256) GEMM: u1 = h0@Wt1, v1 = h0@Wd1 ------
// NOTE: all device-global buffers are referenced INSIDE the kernel (passing a
// __device__ symbol from host silently reads the host shadow via ATS on GB300).
__global__ __launch_bounds__(256) void gemm16_k(const float* __restrict__ Wt1) {
    __shared__ float hs[16 * 64];
    int r0 = blockIdx.x * 16;
    int t = threadIdx.x;
    #pragma unroll
    for (int s = 0; s < 4; s++) {
        int l = t + (s << 8);
        hs[l] = g_h0[(size_t)r0 * 64 + l];
    }
    __syncthreads();
    float au[16], av[16];
    #pragma unroll
    for (int r = 0; r < 16; r++) { au[r] = 0.f; av[r] = 0.f; }
    #pragma unroll 4
    for (int d = 0; d < 64; d++) {
        float wu = Wt1[d * 256 + t];
        float wv = g_Wd1[d * 256 + t];
        #pragma unroll
        for (int r = 0; r < 16; r++) {
            float h = hs[r * 64 + d];
            au[r] = fmaf(h, wu, au[r]);
            av[r] = fmaf(h, wv, av[r]);
        }
    }
    #pragma unroll
    for (int r = 0; r < 16; r++) {
        g_u[(size_t)(r0 + r) * 256 + t] = au[r];
        g_v[(size_t)(r0 + r) * 256 + t] = av[r];
    }
}

// ---------------- distance GEMM (layer1): dist = n_i + n_j - 2 h.h^T ---------
__global__ __launch_bounds__(256) void dist_gemm_k() {
    const int b = blockIdx.z;
    const int i0 = blockIdx.y * 64, j0 = blockIdx.x * 64;
    __shared__ float As[64][65];   // As[d][i]
    __shared__ float Bs[64][65];   // Bs[d][j]
    const float* hb = g_h0 + (size_t)b * NN * 64;
    int t = threadIdx.x;
    #pragma unroll
    for (int s = 0; s < 16; s++) {
        int l = t + (s << 8);
        int r = l >> 6, d = l & 63;
        As[d][r] = hb[(size_t)(i0 + r) * 64 + d];
        Bs[d][r] = hb[(size_t)(j0 + r) * 64 + d];
    }
    __syncthreads();
    int tx = t & 15, ty = t >> 4;
    float acc[4][4];
    #pragma unroll
    for (int r = 0; r < 4; r++)
        #pragma unroll
        for (int c = 0; c < 4; c++) acc[r][c] = 0.f;
    #pragma unroll 8
    for (int d = 0; d < 64; d++) {
        float a0 = As[d][ty * 4 + 0], a1 = As[d][ty * 4 + 1];
        float a2 = As[d][ty * 4 + 2], a3 = As[d][ty * 4 + 3];
        float b0 = Bs[d][tx * 4 + 0], b1 = Bs[d][tx * 4 + 1];
        float b2 = Bs[d][tx * 4 + 2], b3 = Bs[d][tx * 4 + 3];
        acc[0][0] = fmaf(a0, b0, acc[0][0]); acc[0][1] = fmaf(a0, b1, acc[0][1]);
        acc[0][2] = fmaf(a0, b2, acc[0][2]); acc[0][3] = fmaf(a0, b3, acc[0][3]);
        acc[1][0] = fmaf(a1, b0, acc[1][0]); acc[1][1] = fmaf(a1, b1, acc[1][1]);
        acc[1][2] = fmaf(a1, b2, acc[1][2]); acc[1][3] = fmaf(a1, b3, acc[1][3]);
        acc[2][0] = fmaf(a2, b0, acc[2][0]); acc[2][1] = fmaf(a2, b1, acc[2][1]);
        acc[2][2] = fmaf(a2, b2, acc[2][2]); acc[2][3] = fmaf(a2, b3, acc[2][3]);
        acc[3][0] = fmaf(a3, b0, acc[3][0]); acc[3][1] = fmaf(a3, b1, acc[3][1]);
        acc[3][2] = fmaf(a3, b2, acc[3][2]); acc[3][3] = fmaf(a3, b3, acc[3][3]);
    }
    const float* n2 = g_d2 + b * NN;
    float nj0 = n2[j0 + tx * 4 + 0], nj1 = n2[j0 + tx * 4 + 1];
    float nj2 = n2[j0 + tx * 4 + 2], nj3 = n2[j0 + tx * 4 + 3];
    #pragma unroll
    for (int r = 0; r < 4; r++) {
        float ni = n2[i0 + ty * 4 + r];
        float4 o;
        o.x = ni + nj0 - 2.f * acc[r][0];
        o.y = ni + nj1 - 2.f * acc[r][1];
        o.z = ni + nj2 - 2.f * acc[r][2];
        o.w = ni + nj3 - 2.f * acc[r][3];
        *(float4*)&g_dist[((size_t)(b * NN + i0 + ty * 4 + r)) * NN + j0 + tx * 4] = o;
    }
}

// ---------------- top-20 selection (min distance, tie -> lowest index) -------
__device__ __forceinline__ void select20(float* sd, float* rv, int* ri, int* fi_s,
                                         float bestv, int besti, int row) {
    int t = threadIdx.x;
    int* out = g_idx + row * KK;
    for (int k = 0; k < KK; k++) {
        float v = bestv; int i = besti;
        #pragma unroll
        for (int o = 16; o > 0; o >>= 1) {
            float ov = __shfl_down_sync(0xffffffffu, v, o);
            int   oi = __shfl_down_sync(0xffffffffu, i, o);
            if (ov < v || (ov == v && oi < i)) { v = ov; i = oi; }
        }
        if ((t & 31) == 0) { rv[t >> 5] = v; ri[t >> 5] = i; }
        __syncthreads();
        if (t == 0) {
            float bv = rv[0]; int bi = ri[0];
            #pragma unroll
            for (int w = 1; w < 8; w++)
                if (rv[w] < bv || (rv[w] == bv && ri[w] < bi)) { bv = rv[w]; bi = ri[w]; }
            *fi_s = bi;
            out[k] = bi;
        }
        __syncthreads();
        int win = *fi_s;
        if ((win & 255) == t) {   // owner of that stripe rescans
            sd[win] = FINF;
            bestv = FINF; besti = 0x7fffffff;
            #pragma unroll
            for (int s = 0; s < 16; s++) {
                int j = t + (s << 8);
                float dd = sd[j];
                if (dd < bestv) { bestv = dd; besti = j; }
            }
        }
        __syncthreads();
    }
}

// layer0: fused D=3 distance + selection (no dist matrix materialized)
__global__ __launch_bounds__(256) void knn0_k(const float* __restrict__ x) {
    __shared__ float sd[NN];
    __shared__ float rv[8];
    __shared__ int   ri[8];
    __shared__ int   fi_s;
    int row = blockIdx.x;
    int base = row & ~(NN - 1);
    int t = threadIdx.x;
    float x0 = x[row * 3], x1 = x[row * 3 + 1], x2 = x[row * 3 + 2];
    float ni = g_d2[row];
    float bestv = FINF; int besti = 0x7fffffff;
    #pragma unroll 4
    for (int s = 0; s < 16; s++) {
        int j = t + (s << 8);
        const float* xj = x + (size_t)(base + j) * 3;
        float dot = x0 * xj[0] + x1 * xj[1] + x2 * xj[2];
        float dd = ni + g_d2[base + j] - 2.f * dot;
        sd[j] = dd;
        if (dd < bestv) { bestv = dd; besti = j; }
    }
    __syncthreads();
    select20(sd, rv, ri, &fi_s, bestv, besti, row);
}

// layer1: selection over precomputed distance rows
__global__ __launch_bounds__(256) void knn1_k() {
    __shared__ float sd[NN];
    __shared__ float rv[8];
    __shared__ int   ri[8];
    __shared__ int   fi_s;
    int row = blockIdx.x;
    int t = threadIdx.x;
    const float* dr = g_dist + (size_t)row * NN;
    float bestv = FINF; int besti = 0x7fffffff;
    #pragma unroll 4
    for (int s = 0; s < 16; s++) {
        int j = t + (s << 8);
        float dd = dr[j];
        sd[j] = dd;
        if (dd < bestv) { bestv = dd; besti = j; }
    }
    __syncthreads();
    select20(sd, rv, ri, &fi_s, bestv, besti, row);
}

// ---------------- BN statistics over edges (deterministic 2-stage) ----------
template <int C>
__global__ __launch_bounds__(256) void stats_k() {
    constexpr int G = 256 / C;
    int t = threadIdx.x;
    int c = t % C;
    int g = t / C;
    const float* u = g_u;
    const float* v = g_v;
    float s = 0.f, s2 = 0.f;
    for (int p = blockIdx.x * G + g; p < NPTS; p += STATS_BLOCKS * G) {
        int b = p >> 12;
        float uc = u[(size_t)p * C + c];
        const int* ip = g_idx + p * KK;
        #pragma unroll
        for (int k = 0; k < KK; k++) {
            int j = ip[k];
            float m = uc + v[((size_t)((b << 12) + j)) * C + c];
            s += m;
            s2 = fmaf(m, m, s2);
        }
    }
    __shared__ float sh[256], sh2[256];
    sh[t] = s; sh2[t] = s2;
    __syncthreads();
    if (t < C) {
        float S = sh[t], S2 = sh2[t];
        #pragma unroll
        for (int gg = 1; gg < G; gg++) { S += sh[gg * C + t]; S2 += sh2[gg * C + t]; }
        g_part[blockIdx.x * (2 * C) + t] = S;
        g_part[blockIdx.x * (2 * C) + C + t] = S2;
    }
}

template <int C>
__global__ void fin_k(const float* __restrict__ gamma, const float* __restrict__ beta) {
    int c = threadIdx.x;
    float S = 0.f, S2 = 0.f;
    for (int bk = 0; bk < STATS_BLOCKS; bk++) {
        S += g_part[bk * 2 * C + c];
        S2 += g_part[bk * 2 * C + C + c];
    }
    const float inv = 1.f / (float)EDG;
    float mu = S * inv;
    float var = S2 * inv - mu * mu;
    float sc = gamma[c] * rsqrtf(var + 1e-5f);
    g_scale[c] = sc;
    g_shift[c] = beta[c] - mu * sc;
}

// ---------------- max-aggregate + affine + leaky relu ------------------------
template <int C>
__global__ __launch_bounds__(256) void maxagg_k() {
    constexpr int G = 256 / C;
    int t = threadIdx.x;
    int c = t % C;
    int g = t / C;
    int p = blockIdx.x * G + g;
    if (p >= NPTS) return;
    int b = p >> 12;
    const float* u = g_u;
    const float* v = g_v;
    float* out = (C == 64) ? (float*)g_h0 : (float*)g_h1;
    float uc = u[(size_t)p * C + c];
    const int* ip = g_idx + p * KK;
    float mx = -FINF, mn = FINF;
    #pragma unroll
    for (int k = 0; k < KK; k++) {
        int j = ip[k];
        float m = uc + v[((size_t)((b << 12) + j)) * C + c];
        mx = fmaxf(mx, m);
        mn = fminf(mn, m);
    }
    float sc = g_scale[c];
    float M = sc >= 0.f ? mx : mn;
    out[(size_t)p * C + c] = leaky(fmaf(M, sc, g_shift[c]));
}

// ---------------- attention gate + softmax -----------------------------------
__global__ void gate_k(const float* __restrict__ Wg, const float* __restrict__ bg) {
    int gt = blockIdx.x * 256 + threadIdx.x;
    int r = gt >> 5, lane = gt & 31;
    if (r >= NPTS) return;
    const float* h = g_h1 + (size_t)r * 256;
    float s = 0.f;
    #pragma unroll
    for (int q = 0; q < 8; q++) {
        int d = lane + (q << 5);
        s = fmaf(h[d], Wg[d], s);
    }
    #pragma unroll
    for (int o = 16; o; o >>= 1) s += __shfl_down_sync(0xffffffffu, s, o);
    if (lane == 0) {
        float gg = s + bg[0];
        g_gate[r] = gg > 0.f ? gg : 0.f;
    }
}

__global__ void softmax_k() {
    int b = blockIdx.x, t = threadIdx.x;
    __shared__ float sh[256];
    const float* gp = g_gate + (b << 12);
    float* ap = g_alpha + (b << 12);
    float mx = -FINF;
    for (int s = 0; s < 16; s++) mx = fmaxf(mx, gp[t + (s << 8)]);
    sh[t] = mx; __syncthreads();
    for (int o = 128; o; o >>= 1) { if (t < o) sh[t] = fmaxf(sh[t], sh[t + o]); __syncthreads(); }
    float M = sh[0];
    __syncthreads();
    float sum = 0.f;
    for (int s = 0; s < 16; s++) {
        int j = t + (s << 8);
        float e = expf(gp[j] - M);
        ap[j] = e;
        sum += e;
    }
    sh[t] = sum; __syncthreads();
    for (int o = 128; o; o >>= 1) { if (t < o) sh[t] += sh[t + o]; __syncthreads(); }
    float inv = 1.f / sh[0];
    for (int s = 0; s < 16; s++) ap[t + (s << 8)] *= inv;
}

// ---------------- fused feat GEMM + weighted pooling --------------------------
__global__ __launch_bounds__(256) void pool_k(const float* __restrict__ Wf,
                                              const float* __restrict__ bf) {
    int b = blockIdx.x;
    int t = threadIdx.x;
    int ch = blockIdx.y * 256 + t;
    int slab = blockIdx.z;
    __shared__ float hr[16][256];
    __shared__ float al[16];
    float acc = 0.f;
    float bfc = bf[ch];
    for (int gidx = 0; gidx < 8; gidx++) {
        int nb = (slab << 7) + (gidx << 4);
        __syncthreads();
        #pragma unroll
        for (int s = 0; s < 16; s++)
            hr[s][t] = g_h1[((size_t)(b << 12) + nb + s) * 256 + t];
        if (t < 16) al[t] = g_alpha[(b << 12) + nb + t];
        __syncthreads();
        float sacc[16];
        #pragma unroll
        for (int r = 0; r < 16; r++) sacc[r] = bfc;
        #pragma unroll 4
        for (int d = 0; d < 256; d += 4) {
            float w0 = Wf[(d + 0) * 512 + ch];
            float w1 = Wf[(d + 1) * 512 + ch];
            float w2 = Wf[(d + 2) * 512 + ch];
            float w3 = Wf[(d + 3) * 512 + ch];
            #pragma unroll
            for (int r = 0; r < 16; r++) {
                float4 hv = *(const float4*)&hr[r][d];
                sacc[r] = fmaf(hv.x, w0, fmaf(hv.y, w1, fmaf(hv.z, w2, fmaf(hv.w, w3, sacc[r]))));
            }
        }
        #pragma unroll
        for (int r = 0; r < 16; r++) {
            float f = sacc[r] > 0.f ? sacc[r] : 0.f;
            acc = fmaf(al[r], f, acc);
        }
    }
    g_pool[((slab << 2) + b) * 512 + ch] = acc;
}

__global__ void poolred_k() {
    int gid = blockIdx.x * 256 + threadIdx.x;  // BB*512
    if (gid >= BB * 512) return;
    int b = gid >> 9, ch = gid & 511;
    float s = 0.f;
    for (int sl = 0; sl < 32; sl++) s += g_pool[((sl << 2) + b) * 512 + ch];
    g_pooled[gid] = s;
}

__global__ void final_k(const float* __restrict__ Wl, const float* __restrict__ bl,
                        float* __restrict__ out) {
    int b = blockIdx.x, o = threadIdx.x;
    const float* p = g_pooled + b * 512;
    float s = bl[o];
    #pragma unroll 8
    for (int f = 0; f < 512; f++) s = fmaf(p[f], Wl[f * 256 + o], s);
    out[b * 256 + o] = s;
}

// ---------------- launch ------------------------------------------------------
extern "C" void kernel_launch(void* const* d_in, const int* in_sizes, int n_in,
                              void* d_out, int out_size) {
    (void)in_sizes; (void)n_in; (void)out_size;
    const float* x   = (const float*)d_in[0];
    const float* Wt0 = (const float*)d_in[1];
    const float* Wp0 = (const float*)d_in[3];
    const float* g0  = (const float*)d_in[5];
    const float* be0 = (const float*)d_in[6];
    const float* Wt1 = (const float*)d_in[7];
    const float* Wp1 = (const float*)d_in[9];
    const float* g1  = (const float*)d_in[11];
    const float* be1 = (const float*)d_in[12];
    const float* Wg  = (const float*)d_in[13];
    const float* bg  = (const float*)d_in[14];
    const float* Wf  = (const float*)d_in[15];
    const float* bf  = (const float*)d_in[16];
    const float* Wl  = (const float*)d_in[17];
    const float* bl  = (const float*)d_in[18];
    float* out = (float*)d_out;

    // ---- layer 0 ----
    prep_k<<<65, 256>>>(Wt0, Wp0, Wt1, Wp1);
    norms3_k<<<64, 256>>>(x);
    uv0_k<<<NPTS * 64 / 256, 256>>>(x, Wt0);
    knn0_k<<<NPTS, 256>>>(x);
    stats_k<64><<<STATS_BLOCKS, 256>>>();
    fin_k<64><<<1, 64>>>(g0, be0);
    maxagg_k<64><<<NPTS / 4, 256>>>();

    // ---- layer 1 ----
    norms64_k<<<NPTS * 32 / 256, 256>>>();
    gemm16_k<<<NPTS / 16, 256>>>(Wt1);               // u1 & v1 fused
    dist_gemm_k<<<dim3(NN / 64, NN / 64, BB), 256>>>();
    knn1_k<<<NPTS, 256>>>();
    stats_k<256><<<STATS_BLOCKS, 256>>>();
    fin_k<256><<<1, 256>>>(g1, be1);
    maxagg_k<256><<<NPTS, 256>>>();

    // ---- attention pooling + final linear ----
    gate_k<<<NPTS * 32 / 256, 256>>>(Wg, bg);
    softmax_k<<<BB, 256>>>();
    pool_k<<<dim3(BB, 2, 32), 256>>>(Wf, bf);
    poolred_k<<<8, 256>>>();
    final_k<<<BB, 256>>>(Wl, bl, out);
}

// round 3
// speedup vs baseline: 1.1749x; 1.1749x over previous
#include <cuda_runtime.h>
#include <math.h>

#define BB 4
#define NN 4096
#define KK 20
#define NPTS (BB*NN)            // 16384
#define EDG  (NPTS*KK)          // 327680
#define STATS_BLOCKS 512

#define FINF __int_as_float(0x7f800000)
#define ULLMAX 0xFFFFFFFFFFFFFFFFULL

// ---------------- scratch (device globals; no allocations allowed) ----------
__device__ float g_dist[(size_t)BB * NN * NN];   // 268 MB distance matrix (layer 1)
__device__ float g_d2[NPTS];
__device__ int   g_idx[NPTS * KK];
__device__ float g_u[NPTS * 256];
__device__ float g_v[NPTS * 256];
__device__ float g_h0[NPTS * 64];
__device__ float g_h1[NPTS * 256];
__device__ float g_Wd0[3 * 64];
__device__ float g_Wd1[64 * 256];
__device__ float g_part[STATS_BLOCKS * 2 * 256];
__device__ float g_scale[256];
__device__ float g_shift[256];
__device__ float g_gate[NPTS];
__device__ float g_alpha[NPTS];
__device__ float g_pool[32 * BB * 512];
__device__ float g_pooled[BB * 512];

static __device__ __forceinline__ float leaky(float v) { return v > 0.f ? v : 0.2f * v; }

// float -> order-preserving uint (ascending float == ascending uint)
static __device__ __forceinline__ unsigned okey(float f) {
    unsigned u = __float_as_uint(f);
    return u ^ ((unsigned)(((int)u) >> 31) | 0x80000000u);
}

// ---------------- weight prep: Wd = Wp - Wt ---------------------------------
__global__ void prep_k(const float* __restrict__ Wt0, const float* __restrict__ Wp0,
                       const float* __restrict__ Wt1, const float* __restrict__ Wp1) {
    int i = blockIdx.x * 256 + threadIdx.x;
    if (i < 192) g_Wd0[i] = Wp0[i] - Wt0[i];
    int j = i - 192;
    if (j >= 0 && j < 16384) g_Wd1[j] = Wp1[j] - Wt1[j];
}

// ---------------- squared norms ---------------------------------------------
__global__ void norms3_k(const float* __restrict__ x) {
    int r = blockIdx.x * blockDim.x + threadIdx.x;
    if (r >= NPTS) return;
    float a = x[r * 3], b = x[r * 3 + 1], c = x[r * 3 + 2];
    g_d2[r] = a * a + b * b + c * c;
}

__global__ void norms64_k() {
    int gt = blockIdx.x * blockDim.x + threadIdx.x;
    int r = gt >> 5, lane = gt & 31;
    if (r >= NPTS) return;
    const float* h = g_h0 + (size_t)r * 64;
    float a = h[lane], b = h[lane + 32];
    float s = a * a + b * b;
    #pragma unroll
    for (int o = 16; o; o >>= 1) s += __shfl_down_sync(0xffffffffu, s, o);
    if (lane == 0) g_d2[r] = s;
}

// ---------------- layer0 u/v (3->64, trivial) --------------------------------
__global__ void uv0_k(const float* __restrict__ x, const float* __restrict__ Wt0) {
    int gid = blockIdx.x * 256 + threadIdx.x;   // NPTS*64 total
    int r = gid >> 6, c = gid & 63;
    float x0 = x[r * 3], x1 = x[r * 3 + 1], x2 = x[r * 3 + 2];
    g_u[gid] = x0 * Wt0[c] + x1 * Wt0[64 + c] + x2 * Wt0[128 + c];
    g_v[gid] = x0 * g_Wd0[c] + x1 * g_Wd0[64 + c] + x2 * g_Wd0[128 + c];
}

// ---------------- fused 16-row (64->256) GEMM: u1 = h0@Wt1, v1 = h0@Wd1 ------
__global__ __launch_bounds__(256) void gemm16_k(const float* __restrict__ Wt1) {
    __shared__ float hs[16 * 64];
    int r0 = blockIdx.x * 16;
    int t = threadIdx.x;
    #pragma unroll
    for (int s = 0; s < 4; s++) {
        int l = t + (s << 8);
        hs[l] = g_h0[(size_t)r0 * 64 + l];
    }
    __syncthreads();
    float au[16], av[16];
    #pragma unroll
    for (int r = 0; r < 16; r++) { au[r] = 0.f; av[r] = 0.f; }
    #pragma unroll 4
    for (int d = 0; d < 64; d++) {
        float wu = Wt1[d * 256 + t];
        float wv = g_Wd1[d * 256 + t];
        #pragma unroll
        for (int r = 0; r < 16; r++) {
            float h = hs[r * 64 + d];
            au[r] = fmaf(h, wu, au[r]);
            av[r] = fmaf(h, wv, av[r]);
        }
    }
    #pragma unroll
    for (int r = 0; r < 16; r++) {
        g_u[(size_t)(r0 + r) * 256 + t] = au[r];
        g_v[(size_t)(r0 + r) * 256 + t] = av[r];
    }
}

// ---------------- distance GEMM (layer1), symmetric: only ti<=tj tiles -------
__global__ __launch_bounds__(256) void dist_gemm_k() {
    const int b = blockIdx.z;
    const int ti = blockIdx.y, tj = blockIdx.x;
    if (tj < ti) return;
    const int i0 = ti * 64, j0 = tj * 64;
    __shared__ float As[64][65];   // As[d][i]
    __shared__ float Bs[64][65];   // Bs[d][j]
    const float* hb = g_h0 + (size_t)b * NN * 64;
    int t = threadIdx.x;
    #pragma unroll
    for (int s = 0; s < 16; s++) {
        int l = t + (s << 8);
        int r = l >> 6, d = l & 63;
        As[d][r] = hb[(size_t)(i0 + r) * 64 + d];
        Bs[d][r] = hb[(size_t)(j0 + r) * 64 + d];
    }
    __syncthreads();
    int tx = t & 15, ty = t >> 4;
    float acc[4][4];
    #pragma unroll
    for (int r = 0; r < 4; r++)
        #pragma unroll
        for (int c = 0; c < 4; c++) acc[r][c] = 0.f;
    #pragma unroll 8
    for (int d = 0; d < 64; d++) {
        float a0 = As[d][ty * 4 + 0], a1 = As[d][ty * 4 + 1];
        float a2 = As[d][ty * 4 + 2], a3 = As[d][ty * 4 + 3];
        float b0 = Bs[d][tx * 4 + 0], b1 = Bs[d][tx * 4 + 1];
        float b2 = Bs[d][tx * 4 + 2], b3 = Bs[d][tx * 4 + 3];
        acc[0][0] = fmaf(a0, b0, acc[0][0]); acc[0][1] = fmaf(a0, b1, acc[0][1]);
        acc[0][2] = fmaf(a0, b2, acc[0][2]); acc[0][3] = fmaf(a0, b3, acc[0][3]);
        acc[1][0] = fmaf(a1, b0, acc[1][0]); acc[1][1] = fmaf(a1, b1, acc[1][1]);
        acc[1][2] = fmaf(a1, b2, acc[1][2]); acc[1][3] = fmaf(a1, b3, acc[1][3]);
        acc[2][0] = fmaf(a2, b0, acc[2][0]); acc[2][1] = fmaf(a2, b1, acc[2][1]);
        acc[2][2] = fmaf(a2, b2, acc[2][2]); acc[2][3] = fmaf(a2, b3, acc[2][3]);
        acc[3][0] = fmaf(a3, b0, acc[3][0]); acc[3][1] = fmaf(a3, b1, acc[3][1]);
        acc[3][2] = fmaf(a3, b2, acc[3][2]); acc[3][3] = fmaf(a3, b3, acc[3][3]);
    }
    const float* n2 = g_d2 + b * NN;
    float nj0 = n2[j0 + tx * 4 + 0], nj1 = n2[j0 + tx * 4 + 1];
    float nj2 = n2[j0 + tx * 4 + 2], nj3 = n2[j0 + tx * 4 + 3];
    float ov[4][4];
    #pragma unroll
    for (int r = 0; r < 4; r++) {
        float ni = n2[i0 + ty * 4 + r];
        ov[r][0] = ni + nj0 - 2.f * acc[r][0];
        ov[r][1] = ni + nj1 - 2.f * acc[r][1];
        ov[r][2] = ni + nj2 - 2.f * acc[r][2];
        ov[r][3] = ni + nj3 - 2.f * acc[r][3];
        *(float4*)&g_dist[((size_t)(b * NN + i0 + ty * 4 + r)) * NN + j0 + tx * 4] =
            make_float4(ov[r][0], ov[r][1], ov[r][2], ov[r][3]);
    }
    if (ti != tj) {
        // mirror the tile: stage transpose in As (done with its data), coalesced write
        __syncthreads();
        float* Ts = &As[0][0];                 // [64][65] layout
        #pragma unroll
        for (int r = 0; r < 4; r++)
            #pragma unroll
            for (int c = 0; c < 4; c++)
                Ts[(tx * 4 + c) * 65 + (ty * 4 + r)] = ov[r][c];
        __syncthreads();
        #pragma unroll
        for (int s = 0; s < 16; s++) {
            int l = t + (s << 8);
            int jr = l >> 6, ic = l & 63;
            g_dist[((size_t)(b * NN + j0 + jr)) * NN + i0 + ic] = Ts[jr * 65 + ic];
        }
    }
}

// ---------------- radix-select top-KK (min keys; ties -> lowest index) -------
// sk: 4096 order-keys in smem.  Emits KK indices (unordered) to g_idx[row].
// ctl[0]=out slot counter, ctl[1]=candidate counter, ctl[2]=pivot bin, ctl[3]=need
__device__ __forceinline__ void select_topk(unsigned* sk, unsigned long long* cA,
                                            int* hist, int* ctl, int row) {
    int t = threadIdx.x;
    int* out = g_idx + row * KK;
    if (t == 0) { ctl[0] = 0; ctl[1] = 0; }
    hist[t] = 0;
    __syncthreads();
    // level-1 histogram (warp-aggregated atomics)
    #pragma unroll
    for (int s = 0; s < 16; s++) {
        int byte = sk[t + (s << 8)] >> 24;
        unsigned mm = __match_any_sync(0xffffffffu, byte);
        if ((t & 31) == __ffs(mm) - 1) atomicAdd(&hist[byte], __popc(mm));
    }
    __syncthreads();
    // inclusive scan over 256 bins
    for (int off = 1; off < 256; off <<= 1) {
        int add = (t >= off) ? hist[t - off] : 0;
        __syncthreads();
        hist[t] += add;
        __syncthreads();
    }
    {
        int cum = hist[t];
        int prev = t ? hist[t - 1] : 0;
        if (cum >= KK && prev < KK) { ctl[2] = t; ctl[3] = KK - prev; }
    }
    __syncthreads();
    int b1 = ctl[2];
    int need = ctl[3];
    // level-1 emit/collect
    #pragma unroll
    for (int s = 0; s < 16; s++) {
        int j = t + (s << 8);
        unsigned key = sk[j];
        int byte = key >> 24;
        if (byte < b1) {
            int p = atomicAdd(&ctl[0], 1);
            out[p] = j;
        } else if (byte == b1) {
            int p = atomicAdd(&ctl[1], 1);
            cA[p] = ((unsigned long long)key << 32) | (unsigned)j;
        }
    }
    __syncthreads();
    int m = ctl[1];
    // refine by bytes 2..4 until candidates fit one block-width
    for (int lvl = 0; lvl < 3 && m > 256; lvl++) {
        int sh = 48 - 8 * lvl;
        unsigned long long e[16];
        #pragma unroll
        for (int s = 0; s < 16; s++) {
            int i = t + (s << 8);
            e[s] = (i < m) ? cA[i] : ULLMAX;
        }
        hist[t] = 0;
        if (t == 0) ctl[1] = 0;
        __syncthreads();
        #pragma unroll
        for (int s = 0; s < 16; s++) {
            bool valid = (t + (s << 8)) < m;
            unsigned act = __ballot_sync(0xffffffffu, valid);
            if (valid) {
                int byte = (int)((e[s] >> sh) & 255);
                unsigned mm = __match_any_sync(act, byte);
                if ((t & 31) == __ffs(mm) - 1) atomicAdd(&hist[byte], __popc(mm));
            }
        }
        __syncthreads();
        for (int off = 1; off < 256; off <<= 1) {
            int add = (t >= off) ? hist[t - off] : 0;
            __syncthreads();
            hist[t] += add;
            __syncthreads();
        }
        {
            int cum = hist[t];
            int prev = t ? hist[t - 1] : 0;
            if (cum >= need && prev < need) { ctl[2] = t; ctl[3] = need - prev; }
        }
        __syncthreads();
        int b2 = ctl[2];
        need = ctl[3];
        #pragma unroll
        for (int s = 0; s < 16; s++) {
            int i = t + (s << 8);
            if (i < m) {
                int byte = (int)((e[s] >> sh) & 255);
                if (byte < b2) {
                    int p = atomicAdd(&ctl[0], 1);
                    out[p] = (int)(e[s] & 0xffffffffu);
                } else if (byte == b2) {
                    int p = atomicAdd(&ctl[1], 1);
                    cA[p] = e[s];
                }
            }
        }
        __syncthreads();
        m = ctl[1];
    }
    if (m > 256) {
        // degenerate (all keys equal through 4 bytes): serial, never hit on real data
        if (t == 0) {
            int oc = ctl[0];
            for (int k = 0; k < need; k++) {
                unsigned long long best = ULLMAX; int bp = 0;
                for (int i = 0; i < m; i++)
                    if (cA[i] < best) { best = cA[i]; bp = i; }
                out[oc + k] = (int)(best & 0xffffffffu);
                cA[bp] = ULLMAX;
            }
        }
        __syncthreads();
        return;
    }
    // pad to 256 and bitonic sort (u64 order = key then index)
    if (t >= m) cA[t] = ULLMAX;
    __syncthreads();
    for (int k2 = 2; k2 <= 256; k2 <<= 1) {
        for (int j = k2 >> 1; j > 0; j >>= 1) {
            int p = t ^ j;
            if (p > t) {
                unsigned long long a = cA[t], bb = cA[p];
                bool up = ((t & k2) == 0);
                if ((a > bb) == up) { cA[t] = bb; cA[p] = a; }
            }
            __syncthreads();
        }
    }
    int oc = ctl[0];
    if (t < need) out[oc + t] = (int)(cA[t] & 0xffffffffu);
}

// layer0: fused D=3 distance + radix selection
__global__ __launch_bounds__(256) void knn0_k(const float* __restrict__ x) {
    __shared__ unsigned sk[NN];
    __shared__ unsigned long long cA[NN];
    __shared__ int hist[256];
    __shared__ int ctl[4];
    int row = blockIdx.x;
    int base = row & ~(NN - 1);
    int t = threadIdx.x;
    float x0 = x[row * 3], x1 = x[row * 3 + 1], x2 = x[row * 3 + 2];
    float ni = g_d2[row];
    #pragma unroll 4
    for (int s = 0; s < 16; s++) {
        int j = t + (s << 8);
        const float* xj = x + (size_t)(base + j) * 3;
        float dot = x0 * xj[0] + x1 * xj[1] + x2 * xj[2];
        float dd = ni + g_d2[base + j] - 2.f * dot;
        sk[j] = okey(dd);
    }
    __syncthreads();
    select_topk(sk, cA, hist, ctl, row);
}

// layer1: radix selection over precomputed distance rows
__global__ __launch_bounds__(256) void knn1_k() {
    __shared__ unsigned sk[NN];
    __shared__ unsigned long long cA[NN];
    __shared__ int hist[256];
    __shared__ int ctl[4];
    int row = blockIdx.x;
    int t = threadIdx.x;
    const float* dr = g_dist + (size_t)row * NN;
    #pragma unroll 4
    for (int s = 0; s < 16; s++) {
        int j = t + (s << 8);
        sk[j] = okey(dr[j]);
    }
    __syncthreads();
    select_topk(sk, cA, hist, ctl, row);
}

// ---------------- BN statistics over edges (deterministic 2-stage) ----------
template <int C>
__global__ __launch_bounds__(256) void stats_k() {
    constexpr int G = 256 / C;
    int t = threadIdx.x;
    int c = t % C;
    int g = t / C;
    const float* u = g_u;
    const float* v = g_v;
    float s = 0.f, s2 = 0.f;
    for (int p = blockIdx.x * G + g; p < NPTS; p += STATS_BLOCKS * G) {
        int b = p >> 12;
        float uc = u[(size_t)p * C + c];
        const int* ip = g_idx + p * KK;
        #pragma unroll
        for (int k = 0; k < KK; k++) {
            int j = ip[k];
            float m = uc + v[((size_t)((b << 12) + j)) * C + c];
            s += m;
            s2 = fmaf(m, m, s2);
        }
    }
    __shared__ float sh[256], sh2[256];
    sh[t] = s; sh2[t] = s2;
    __syncthreads();
    if (t < C) {
        float S = sh[t], S2 = sh2[t];
        #pragma unroll
        for (int gg = 1; gg < G; gg++) { S += sh[gg * C + t]; S2 += sh2[gg * C + t]; }
        g_part[blockIdx.x * (2 * C) + t] = S;
        g_part[blockIdx.x * (2 * C) + C + t] = S2;
    }
}

template <int C>
__global__ void fin_k(const float* __restrict__ gamma, const float* __restrict__ beta) {
    int c = threadIdx.x;
    float S = 0.f, S2 = 0.f;
    for (int bk = 0; bk < STATS_BLOCKS; bk++) {
        S += g_part[bk * 2 * C + c];
        S2 += g_part[bk * 2 * C + C + c];
    }
    const float inv = 1.f / (float)EDG;
    float mu = S * inv;
    float var = S2 * inv - mu * mu;
    float sc = gamma[c] * rsqrtf(var + 1e-5f);
    g_scale[c] = sc;
    g_shift[c] = beta[c] - mu * sc;
}

// ---------------- max-aggregate + affine + leaky relu ------------------------
template <int C>
__global__ __launch_bounds__(256) void maxagg_k() {
    constexpr int G = 256 / C;
    int t = threadIdx.x;
    int c = t % C;
    int g = t / C;
    int p = blockIdx.x * G + g;
    if (p >= NPTS) return;
    int b = p >> 12;
    const float* u = g_u;
    const float* v = g_v;
    float* out = (C == 64) ? (float*)g_h0 : (float*)g_h1;
    float uc = u[(size_t)p * C + c];
    const int* ip = g_idx + p * KK;
    float mx = -FINF, mn = FINF;
    #pragma unroll
    for (int k = 0; k < KK; k++) {
        int j = ip[k];
        float m = uc + v[((size_t)((b << 12) + j)) * C + c];
        mx = fmaxf(mx, m);
        mn = fminf(mn, m);
    }
    float sc = g_scale[c];
    float M = sc >= 0.f ? mx : mn;
    out[(size_t)p * C + c] = leaky(fmaf(M, sc, g_shift[c]));
}

// ---------------- attention gate + softmax -----------------------------------
__global__ void gate_k(const float* __restrict__ Wg, const float* __restrict__ bg) {
    int gt = blockIdx.x * 256 + threadIdx.x;
    int r = gt >> 5, lane = gt & 31;
    if (r >= NPTS) return;
    const float* h = g_h1 + (size_t)r * 256;
    float s = 0.f;
    #pragma unroll
    for (int q = 0; q < 8; q++) {
        int d = lane + (q << 5);
        s = fmaf(h[d], Wg[d], s);
    }
    #pragma unroll
    for (int o = 16; o; o >>= 1) s += __shfl_down_sync(0xffffffffu, s, o);
    if (lane == 0) {
        float gg = s + bg[0];
        g_gate[r] = gg > 0.f ? gg : 0.f;
    }
}

__global__ void softmax_k() {
    int b = blockIdx.x, t = threadIdx.x;
    __shared__ float sh[256];
    const float* gp = g_gate + (b << 12);
    float* ap = g_alpha + (b << 12);
    float mx = -FINF;
    for (int s = 0; s < 16; s++) mx = fmaxf(mx, gp[t + (s << 8)]);
    sh[t] = mx; __syncthreads();
    for (int o = 128; o; o >>= 1) { if (t < o) sh[t] = fmaxf(sh[t], sh[t + o]); __syncthreads(); }
    float M = sh[0];
    __syncthreads();
    float sum = 0.f;
    for (int s = 0; s < 16; s++) {
        int j = t + (s << 8);
        float e = expf(gp[j] - M);
        ap[j] = e;
        sum += e;
    }
    sh[t] = sum; __syncthreads();
    for (int o = 128; o; o >>= 1) { if (t < o) sh[t] += sh[t + o]; __syncthreads(); }
    float inv = 1.f / sh[0];
    for (int s = 0; s < 16; s++) ap[t + (s << 8)] *= inv;
}

// ---------------- fused feat GEMM + weighted pooling --------------------------
__global__ __launch_bounds__(256) void pool_k(const float* __restrict__ Wf,
                                              const float* __restrict__ bf) {
    int b = blockIdx.x;
    int t = threadIdx.x;
    int ch = blockIdx.y * 256 + t;
    int slab = blockIdx.z;
    __shared__ float hr[16][256];
    __shared__ float al[16];
    float acc = 0.f;
    float bfc = bf[ch];
    for (int gidx = 0; gidx < 8; gidx++) {
        int nb = (slab << 7) + (gidx << 4);
        __syncthreads();
        #pragma unroll
        for (int s = 0; s < 16; s++)
            hr[s][t] = g_h1[((size_t)(b << 12) + nb + s) * 256 + t];
        if (t < 16) al[t] = g_alpha[(b << 12) + nb + t];
        __syncthreads();
        float sacc[16];
        #pragma unroll
        for (int r = 0; r < 16; r++) sacc[r] = bfc;
        #pragma unroll 4
        for (int d = 0; d < 256; d += 4) {
            float w0 = Wf[(d + 0) * 512 + ch];
            float w1 = Wf[(d + 1) * 512 + ch];
            float w2 = Wf[(d + 2) * 512 + ch];
            float w3 = Wf[(d + 3) * 512 + ch];
            #pragma unroll
            for (int r = 0; r < 16; r++) {
                float4 hv = *(const float4*)&hr[r][d];
                sacc[r] = fmaf(hv.x, w0, fmaf(hv.y, w1, fmaf(hv.z, w2, fmaf(hv.w, w3, sacc[r]))));
            }
        }
        #pragma unroll
        for (int r = 0; r < 16; r++) {
            float f = sacc[r] > 0.f ? sacc[r] : 0.f;
            acc = fmaf(al[r], f, acc);
        }
    }
    g_pool[((slab << 2) + b) * 512 + ch] = acc;
}

__global__ void poolred_k() {
    int gid = blockIdx.x * 256 + threadIdx.x;  // BB*512
    if (gid >= BB * 512) return;
    int b = gid >> 9, ch = gid & 511;
    float s = 0.f;
    for (int sl = 0; sl < 32; sl++) s += g_pool[((sl << 2) + b) * 512 + ch];
    g_pooled[gid] = s;
}

__global__ void final_k(const float* __restrict__ Wl, const float* __restrict__ bl,
                        float* __restrict__ out) {
    int b = blockIdx.x, o = threadIdx.x;
    const float* p = g_pooled + b * 512;
    float s = bl[o];
    #pragma unroll 8
    for (int f = 0; f < 512; f++) s = fmaf(p[f], Wl[f * 256 + o], s);
    out[b * 256 + o] = s;
}

// ---------------- launch ------------------------------------------------------
extern "C" void kernel_launch(void* const* d_in, const int* in_sizes, int n_in,
                              void* d_out, int out_size) {
    (void)in_sizes; (void)n_in; (void)out_size;
    const float* x   = (const float*)d_in[0];
    const float* Wt0 = (const float*)d_in[1];
    const float* Wp0 = (const float*)d_in[3];
    const float* g0  = (const float*)d_in[5];
    const float* be0 = (const float*)d_in[6];
    const float* Wt1 = (const float*)d_in[7];
    const float* Wp1 = (const float*)d_in[9];
    const float* g1  = (const float*)d_in[11];
    const float* be1 = (const float*)d_in[12];
    const float* Wg  = (const float*)d_in[13];
    const float* bg  = (const float*)d_in[14];
    const float* Wf  = (const float*)d_in[15];
    const float* bf  = (const float*)d_in[16];
    const float* Wl  = (const float*)d_in[17];
    const float* bl  = (const float*)d_in[18];
    float* out = (float*)d_out;

    // ---- layer 0 ----
    prep_k<<<65, 256>>>(Wt0, Wp0, Wt1, Wp1);
    norms3_k<<<64, 256>>>(x);
    uv0_k<<<NPTS * 64 / 256, 256>>>(x, Wt0);
    knn0_k<<<NPTS, 256>>>(x);
    stats_k<64><<<STATS_BLOCKS, 256>>>();
    fin_k<64><<<1, 64>>>(g0, be0);
    maxagg_k<64><<<NPTS / 4, 256>>>();

    // ---- layer 1 ----
    norms64_k<<<NPTS * 32 / 256, 256>>>();
    gemm16_k<<<NPTS / 16, 256>>>(Wt1);               // u1 & v1 fused
    dist_gemm_k<<<dim3(NN / 64, NN / 64, BB), 256>>>();
    knn1_k<<<NPTS, 256>>>();
    stats_k<256><<<STATS_BLOCKS, 256>>>();
    fin_k<256><<<1, 256>>>(g1, be1);
    maxagg_k<256><<<NPTS, 256>>>();

    // ---- attention pooling + final linear ----
    gate_k<<<NPTS * 32 / 256, 256>>>(Wg, bg);
    softmax_k<<<BB, 256>>>();
    pool_k<<<dim3(BB, 2, 32), 256>>>(Wf, bf);
    poolred_k<<<8, 256>>>();
    final_k<<<BB, 256>>>(Wl, bl, out);
}

// round 4
// speedup vs baseline: 1.3028x; 1.1088x over previous
#include <cuda_runtime.h>
#include <math.h>

#define BB 4
#define NN 4096
#define KK 20
#define NPTS (BB*NN)            // 16384
#define EDG  (NPTS*KK)          // 327680
#define STATS_BLOCKS 512

#define FINF __int_as_float(0x7f800000)
#define ULLMAX 0xFFFFFFFFFFFFFFFFULL

// ---------------- scratch (device globals; no allocations allowed) ----------
__device__ float g_dist[(size_t)BB * NN * NN];   // 268 MB distance matrix (layer 1)
__device__ float g_d2[NPTS];
__device__ int   g_idx[NPTS * KK];
__device__ float g_u[NPTS * 256];
__device__ float g_v[NPTS * 256];
__device__ float g_vmax[NPTS * 256];
__device__ float g_vmin[NPTS * 256];
__device__ float g_h0[NPTS * 64];
__device__ float g_h1[NPTS * 256];
__device__ float g_Wd0[3 * 64];
__device__ float g_Wd1[64 * 256];
__device__ float g_part[STATS_BLOCKS * 2 * 256];
__device__ float g_scale[256];
__device__ float g_shift[256];
__device__ float g_gate[NPTS];
__device__ float g_alpha[NPTS];
__device__ float g_pool[32 * BB * 512];
__device__ float g_pooled[BB * 512];

static __device__ __forceinline__ float leaky(float v) { return v > 0.f ? v : 0.2f * v; }

// float -> order-preserving uint (ascending float == ascending uint)
static __device__ __forceinline__ unsigned okey(float f) {
    unsigned u = __float_as_uint(f);
    return u ^ ((unsigned)(((int)u) >> 31) | 0x80000000u);
}

// ---------------- weight prep: Wd = Wp - Wt ---------------------------------
__global__ void prep_k(const float* __restrict__ Wt0, const float* __restrict__ Wp0,
                       const float* __restrict__ Wt1, const float* __restrict__ Wp1) {
    int i = blockIdx.x * 256 + threadIdx.x;
    if (i < 192) g_Wd0[i] = Wp0[i] - Wt0[i];
    int j = i - 192;
    if (j >= 0 && j < 16384) g_Wd1[j] = Wp1[j] - Wt1[j];
}

// ---------------- squared norms ---------------------------------------------
__global__ void norms3_k(const float* __restrict__ x) {
    int r = blockIdx.x * blockDim.x + threadIdx.x;
    if (r >= NPTS) return;
    float a = x[r * 3], b = x[r * 3 + 1], c = x[r * 3 + 2];
    g_d2[r] = a * a + b * b + c * c;
}

__global__ void norms64_k() {
    int gt = blockIdx.x * blockDim.x + threadIdx.x;
    int r = gt >> 5, lane = gt & 31;
    if (r >= NPTS) return;
    const float* h = g_h0 + (size_t)r * 64;
    float a = h[lane], b = h[lane + 32];
    float s = a * a + b * b;
    #pragma unroll
    for (int o = 16; o; o >>= 1) s += __shfl_down_sync(0xffffffffu, s, o);
    if (lane == 0) g_d2[r] = s;
}

// ---------------- layer0 u/v (3->64, trivial) --------------------------------
__global__ void uv0_k(const float* __restrict__ x, const float* __restrict__ Wt0) {
    int gid = blockIdx.x * 256 + threadIdx.x;   // NPTS*64 total
    int r = gid >> 6, c = gid & 63;
    float x0 = x[r * 3], x1 = x[r * 3 + 1], x2 = x[r * 3 + 2];
    g_u[gid] = x0 * Wt0[c] + x1 * Wt0[64 + c] + x2 * Wt0[128 + c];
    g_v[gid] = x0 * g_Wd0[c] + x1 * g_Wd0[64 + c] + x2 * g_Wd0[128 + c];
}

// ---------------- fused 16-row (64->256) GEMM: u1 = h0@Wt1, v1 = h0@Wd1 ------
__global__ __launch_bounds__(256) void gemm16_k(const float* __restrict__ Wt1) {
    __shared__ float hs[16 * 64];
    int r0 = blockIdx.x * 16;
    int t = threadIdx.x;
    #pragma unroll
    for (int s = 0; s < 4; s++) {
        int l = t + (s << 8);
        hs[l] = g_h0[(size_t)r0 * 64 + l];
    }
    __syncthreads();
    float au[16], av[16];
    #pragma unroll
    for (int r = 0; r < 16; r++) { au[r] = 0.f; av[r] = 0.f; }
    #pragma unroll 4
    for (int d = 0; d < 64; d++) {
        float wu = Wt1[d * 256 + t];
        float wv = g_Wd1[d * 256 + t];
        #pragma unroll
        for (int r = 0; r < 16; r++) {
            float h = hs[r * 64 + d];
            au[r] = fmaf(h, wu, au[r]);
            av[r] = fmaf(h, wv, av[r]);
        }
    }
    #pragma unroll
    for (int r = 0; r < 16; r++) {
        g_u[(size_t)(r0 + r) * 256 + t] = au[r];
        g_v[(size_t)(r0 + r) * 256 + t] = av[r];
    }
}

// ---------------- distance GEMM (layer1), triangular tile grid ---------------
static __device__ __forceinline__ int tri_start(int ti) {
    return ti * 64 - (ti * (ti - 1)) / 2;   // pairs with first index < ti
}

__global__ __launch_bounds__(256) void dist_gemm_k() {
    const int b = blockIdx.y;
    int l = blockIdx.x;                    // 0..2079
    int ti = (int)((129.0f - sqrtf(129.0f * 129.0f - 8.0f * (float)l)) * 0.5f);
    if (ti > 63) ti = 63;
    while (ti < 63 && tri_start(ti + 1) <= l) ti++;
    while (ti > 0 && tri_start(ti) > l) ti--;
    int tj = ti + (l - tri_start(ti));
    const int i0 = ti * 64, j0 = tj * 64;
    __shared__ float As[64][65];   // As[d][i]
    __shared__ float Bs[64][65];   // Bs[d][j]
    const float* hb = g_h0 + (size_t)b * NN * 64;
    int t = threadIdx.x;
    #pragma unroll
    for (int s = 0; s < 16; s++) {
        int ll = t + (s << 8);
        int r = ll >> 6, d = ll & 63;
        As[d][r] = hb[(size_t)(i0 + r) * 64 + d];
        Bs[d][r] = hb[(size_t)(j0 + r) * 64 + d];
    }
    __syncthreads();
    int tx = t & 15, ty = t >> 4;
    float acc[4][4];
    #pragma unroll
    for (int r = 0; r < 4; r++)
        #pragma unroll
        for (int c = 0; c < 4; c++) acc[r][c] = 0.f;
    #pragma unroll 8
    for (int d = 0; d < 64; d++) {
        float a0 = As[d][ty * 4 + 0], a1 = As[d][ty * 4 + 1];
        float a2 = As[d][ty * 4 + 2], a3 = As[d][ty * 4 + 3];
        float b0 = Bs[d][tx * 4 + 0], b1 = Bs[d][tx * 4 + 1];
        float b2 = Bs[d][tx * 4 + 2], b3 = Bs[d][tx * 4 + 3];
        acc[0][0] = fmaf(a0, b0, acc[0][0]); acc[0][1] = fmaf(a0, b1, acc[0][1]);
        acc[0][2] = fmaf(a0, b2, acc[0][2]); acc[0][3] = fmaf(a0, b3, acc[0][3]);
        acc[1][0] = fmaf(a1, b0, acc[1][0]); acc[1][1] = fmaf(a1, b1, acc[1][1]);
        acc[1][2] = fmaf(a1, b2, acc[1][2]); acc[1][3] = fmaf(a1, b3, acc[1][3]);
        acc[2][0] = fmaf(a2, b0, acc[2][0]); acc[2][1] = fmaf(a2, b1, acc[2][1]);
        acc[2][2] = fmaf(a2, b2, acc[2][2]); acc[2][3] = fmaf(a2, b3, acc[2][3]);
        acc[3][0] = fmaf(a3, b0, acc[3][0]); acc[3][1] = fmaf(a3, b1, acc[3][1]);
        acc[3][2] = fmaf(a3, b2, acc[3][2]); acc[3][3] = fmaf(a3, b3, acc[3][3]);
    }
    const float* n2 = g_d2 + b * NN;
    float nj0 = n2[j0 + tx * 4 + 0], nj1 = n2[j0 + tx * 4 + 1];
    float nj2 = n2[j0 + tx * 4 + 2], nj3 = n2[j0 + tx * 4 + 3];
    float ov[4][4];
    #pragma unroll
    for (int r = 0; r < 4; r++) {
        float ni = n2[i0 + ty * 4 + r];
        ov[r][0] = ni + nj0 - 2.f * acc[r][0];
        ov[r][1] = ni + nj1 - 2.f * acc[r][1];
        ov[r][2] = ni + nj2 - 2.f * acc[r][2];
        ov[r][3] = ni + nj3 - 2.f * acc[r][3];
        *(float4*)&g_dist[((size_t)(b * NN + i0 + ty * 4 + r)) * NN + j0 + tx * 4] =
            make_float4(ov[r][0], ov[r][1], ov[r][2], ov[r][3]);
    }
    if (ti != tj) {
        __syncthreads();
        float* Ts = &As[0][0];                 // reuse [64][65]
        #pragma unroll
        for (int r = 0; r < 4; r++)
            #pragma unroll
            for (int c = 0; c < 4; c++)
                Ts[(tx * 4 + c) * 65 + (ty * 4 + r)] = ov[r][c];
        __syncthreads();
        #pragma unroll
        for (int s = 0; s < 16; s++) {
            int ll = t + (s << 8);
            int jr = ll >> 6, ic = ll & 63;
            g_dist[((size_t)(b * NN + j0 + jr)) * NN + i0 + ic] = Ts[jr * 65 + ic];
        }
    }
}

// ---------------- fast 256-bin inclusive scan (2 syncs) ----------------------
static __device__ __forceinline__ void scan256(int* hist, int* wsum) {
    int t = threadIdx.x;
    int w = t >> 5, lane = t & 31;
    int v = hist[t];
    #pragma unroll
    for (int off = 1; off < 32; off <<= 1) {
        int n = __shfl_up_sync(0xffffffffu, v, off);
        if (lane >= off) v += n;
    }
    if (lane == 31) wsum[w] = v;
    __syncthreads();
    if (t < 8) {
        int s = wsum[t];
        #pragma unroll
        for (int off = 1; off < 8; off <<= 1) {
            int n = __shfl_up_sync(0xffu, s, off);
            if (t >= off) s += n;
        }
        wsum[t] = s;
    }
    __syncthreads();
    hist[t] = v + (w > 0 ? wsum[w - 1] : 0);
    __syncthreads();
}

// ---------------- radix-select top-KK (min keys; ties -> lowest index) -------
// sk: 4096 order-keys.  cIdx: candidate index buffer.  Emits KK indices
// (unordered set) to g_idx[row].
__device__ __forceinline__ void select_topk(unsigned* sk, int* cIdx,
                                            unsigned long long* sortbuf,
                                            int* hist, int* wsum, int* ctl, int row) {
    int t = threadIdx.x;
    int* out = g_idx + row * KK;
    hist[t] = 0;
    if (t == 0) { ctl[0] = 0; ctl[1] = 0; }
    __syncthreads();
    // level-1 histogram on top byte (warp-aggregated atomics)
    #pragma unroll
    for (int s = 0; s < 16; s++) {
        int byte = sk[t + (s << 8)] >> 24;
        unsigned mm = __match_any_sync(0xffffffffu, byte);
        if ((t & 31) == __ffs(mm) - 1) atomicAdd(&hist[byte], __popc(mm));
    }
    __syncthreads();
    scan256(hist, wsum);
    {
        int cum = hist[t], prev = t ? hist[t - 1] : 0;
        if (cum >= KK && prev < KK) { ctl[2] = t; ctl[3] = KK - prev; }
    }
    __syncthreads();
    int b1 = ctl[2];
    int need = ctl[3];
    #pragma unroll
    for (int s = 0; s < 16; s++) {
        int j = t + (s << 8);
        int byte = sk[j] >> 24;
        if (byte < b1) {
            out[atomicAdd(&ctl[0], 1)] = j;
        } else if (byte == b1) {
            cIdx[atomicAdd(&ctl[1], 1)] = j;
        }
    }
    __syncthreads();
    int m = ctl[1];
    // refine by bytes 2..4 while too many candidates
    for (int lvl = 0; lvl < 3 && m > 256; lvl++) {
        int sh = 16 - 8 * lvl;
        int idxr[16];
        int cnt = 0;
        for (int i = t; i < m; i += 256) idxr[cnt++] = cIdx[i];
        hist[t] = 0;
        if (t == 0) ctl[1] = 0;
        __syncthreads();
        for (int q = 0; q < cnt; q++) {
            int byte = (int)((sk[idxr[q]] >> sh) & 255u);
            unsigned act = __activemask();
            unsigned mm = __match_any_sync(act, byte);
            if ((__ffs(mm) - 1) == (t & 31)) atomicAdd(&hist[byte], __popc(mm));
        }
        __syncthreads();
        scan256(hist, wsum);
        {
            int cum = hist[t], prev = t ? hist[t - 1] : 0;
            if (cum >= need && prev < need) { ctl[2] = t; ctl[3] = need - prev; }
        }
        __syncthreads();
        int b2 = ctl[2];
        need = ctl[3];
        for (int q = 0; q < cnt; q++) {
            int j = idxr[q];
            int byte = (int)((sk[j] >> sh) & 255u);
            if (byte < b2) {
                out[atomicAdd(&ctl[0], 1)] = j;
            } else if (byte == b2) {
                cIdx[atomicAdd(&ctl[1], 1)] = j;
            }
        }
        __syncthreads();
        m = ctl[1];
    }
    int oc = ctl[0];
    if (m > 256) {
        // all 32 key bits equal among candidates -> pick smallest indices (serial, ~never)
        if (t == 0) {
            for (int k = 0; k < need; k++) {
                int best = 0x7fffffff, bp = -1;
                for (int i = 0; i < m; i++)
                    if (cIdx[i] >= 0 && cIdx[i] < best) { best = cIdx[i]; bp = i; }
                out[oc + k] = best;
                cIdx[bp] = -1;
            }
        }
        __syncthreads();
        return;
    }
    // bitonic sort of (key, idx) u64s, take 'need' smallest
    sortbuf[t] = (t < m) ? (((unsigned long long)sk[cIdx[t]] << 32) | (unsigned)cIdx[t])
                         : ULLMAX;
    __syncthreads();
    for (int k2 = 2; k2 <= 256; k2 <<= 1) {
        for (int j = k2 >> 1; j > 0; j >>= 1) {
            int p = t ^ j;
            if (p > t) {
                unsigned long long a = sortbuf[t], bb = sortbuf[p];
                bool up = ((t & k2) == 0);
                if ((a > bb) == up) { sortbuf[t] = bb; sortbuf[p] = a; }
            }
            __syncthreads();
        }
    }
    if (t < need) out[oc + t] = (int)(sortbuf[t] & 0xffffffffu);
}

// layer0: fused D=3 distance + radix selection
__global__ __launch_bounds__(256, 6) void knn0_k(const float* __restrict__ x) {
    __shared__ unsigned sk[NN];
    __shared__ int cIdx[NN];
    __shared__ unsigned long long sortbuf[256];
    __shared__ int hist[256];
    __shared__ int wsum[8];
    __shared__ int ctl[4];
    int row = blockIdx.x;
    int base = row & ~(NN - 1);
    int t = threadIdx.x;
    float x0 = x[row * 3], x1 = x[row * 3 + 1], x2 = x[row * 3 + 2];
    float ni = g_d2[row];
    #pragma unroll 4
    for (int s = 0; s < 16; s++) {
        int j = t + (s << 8);
        const float* xj = x + (size_t)(base + j) * 3;
        float dot = x0 * xj[0] + x1 * xj[1] + x2 * xj[2];
        float dd = ni + g_d2[base + j] - 2.f * dot;
        sk[j] = okey(dd);
    }
    __syncthreads();
    select_topk(sk, cIdx, sortbuf, hist, wsum, ctl, row);
}

// layer1: radix selection over precomputed distance rows
__global__ __launch_bounds__(256, 6) void knn1_k() {
    __shared__ unsigned sk[NN];
    __shared__ int cIdx[NN];
    __shared__ unsigned long long sortbuf[256];
    __shared__ int hist[256];
    __shared__ int wsum[8];
    __shared__ int ctl[4];
    int row = blockIdx.x;
    int t = threadIdx.x;
    const float4* dr = (const float4*)(g_dist + (size_t)row * NN);
    #pragma unroll 4
    for (int s = 0; s < 4; s++) {
        int j4 = t + (s << 8);
        float4 d4 = dr[j4];
        sk[j4 * 4 + 0] = okey(d4.x);
        sk[j4 * 4 + 1] = okey(d4.y);
        sk[j4 * 4 + 2] = okey(d4.z);
        sk[j4 * 4 + 3] = okey(d4.w);
    }
    __syncthreads();
    select_topk(sk, cIdx, sortbuf, hist, wsum, ctl, row);
}

// ---------------- fused gather: BN stats + per-point neighbor vmax/vmin ------
// sum_edges(m) = sum_i [20*u_i + S_i],  sum_edges(m^2) = sum_i [20*u_i^2 + 2*u_i*S_i + Q_i]
template <int C>
__global__ __launch_bounds__(256) void gather_k() {
    constexpr int G = 256 / C;
    int t = threadIdx.x;
    int c = t % C;
    int g = t / C;
    float s = 0.f, s2 = 0.f;
    for (int p = blockIdx.x * G + g; p < NPTS; p += STATS_BLOCKS * G) {
        int b = p >> 12;
        float uc = g_u[(size_t)p * C + c];
        const int* ip = g_idx + p * KK;
        float S = 0.f, Q = 0.f, mx = -FINF, mn = FINF;
        #pragma unroll
        for (int k = 0; k < KK; k++) {
            int j = ip[k];
            float v = g_v[((size_t)((b << 12) + j)) * C + c];
            S += v;
            Q = fmaf(v, v, Q);
            mx = fmaxf(mx, v);
            mn = fminf(mn, v);
        }
        g_vmax[(size_t)p * C + c] = mx;
        g_vmin[(size_t)p * C + c] = mn;
        s += fmaf(20.f, uc, S);
        s2 += fmaf(20.f * uc, uc, fmaf(2.f * uc, S, Q));
    }
    __shared__ float sh[256], sh2[256];
    sh[t] = s; sh2[t] = s2;
    __syncthreads();
    if (t < C) {
        float S = sh[t], S2 = sh2[t];
        #pragma unroll
        for (int gg = 1; gg < G; gg++) { S += sh[gg * C + t]; S2 += sh2[gg * C + t]; }
        g_part[blockIdx.x * (2 * C) + t] = S;
        g_part[blockIdx.x * (2 * C) + C + t] = S2;
    }
}

template <int C>
__global__ void fin_k(const float* __restrict__ gamma, const float* __restrict__ beta) {
    int c = threadIdx.x;
    float S = 0.f, S2 = 0.f;
    for (int bk = 0; bk < STATS_BLOCKS; bk++) {
        S += g_part[bk * 2 * C + c];
        S2 += g_part[bk * 2 * C + C + c];
    }
    const float inv = 1.f / (float)EDG;
    float mu = S * inv;
    float var = S2 * inv - mu * mu;
    float sc = gamma[c] * rsqrtf(var + 1e-5f);
    g_scale[c] = sc;
    g_shift[c] = beta[c] - mu * sc;
}

// ---------------- finish: h = leaky(scale*(u + vmax/vmin) + shift) -----------
template <int C>
__global__ void finish_k() {
    int gid = blockIdx.x * 256 + threadIdx.x;    // NPTS*C
    int c = gid & (C - 1);
    float sc = g_scale[c];
    float vm = (sc >= 0.f) ? g_vmax[gid] : g_vmin[gid];
    float M = g_u[gid] + vm;
    float* out = (C == 64) ? (float*)g_h0 : (float*)g_h1;
    out[gid] = leaky(fmaf(M, sc, g_shift[c]));
}

// ---------------- attention gate + softmax -----------------------------------
__global__ void gate_k(const float* __restrict__ Wg, const float* __restrict__ bg) {
    int gt = blockIdx.x * 256 + threadIdx.x;
    int r = gt >> 5, lane = gt & 31;
    if (r >= NPTS) return;
    const float* h = g_h1 + (size_t)r * 256;
    float s = 0.f;
    #pragma unroll
    for (int q = 0; q < 8; q++) {
        int d = lane + (q << 5);
        s = fmaf(h[d], Wg[d], s);
    }
    #pragma unroll
    for (int o = 16; o; o >>= 1) s += __shfl_down_sync(0xffffffffu, s, o);
    if (lane == 0) {
        float gg = s + bg[0];
        g_gate[r] = gg > 0.f ? gg : 0.f;
    }
}

__global__ void softmax_k() {
    int b = blockIdx.x, t = threadIdx.x;
    __shared__ float sh[256];
    const float* gp = g_gate + (b << 12);
    float* ap = g_alpha + (b << 12);
    float mx = -FINF;
    for (int s = 0; s < 16; s++) mx = fmaxf(mx, gp[t + (s << 8)]);
    sh[t] = mx; __syncthreads();
    for (int o = 128; o; o >>= 1) { if (t < o) sh[t] = fmaxf(sh[t], sh[t + o]); __syncthreads(); }
    float M = sh[0];
    __syncthreads();
    float sum = 0.f;
    for (int s = 0; s < 16; s++) {
        int j = t + (s << 8);
        float e = expf(gp[j] - M);
        ap[j] = e;
        sum += e;
    }
    sh[t] = sum; __syncthreads();
    for (int o = 128; o; o >>= 1) { if (t < o) sh[t] += sh[t + o]; __syncthreads(); }
    float inv = 1.f / sh[0];
    for (int s = 0; s < 16; s++) ap[t + (s << 8)] *= inv;
}

// ---------------- fused feat GEMM + weighted pooling --------------------------
__global__ __launch_bounds__(256) void pool_k(const float* __restrict__ Wf,
                                              const float* __restrict__ bf) {
    int b = blockIdx.x;
    int t = threadIdx.x;
    int ch = blockIdx.y * 256 + t;
    int slab = blockIdx.z;
    __shared__ float hr[16][256];
    __shared__ float al[16];
    float acc = 0.f;
    float bfc = bf[ch];
    for (int gidx = 0; gidx < 8; gidx++) {
        int nb = (slab << 7) + (gidx << 4);
        __syncthreads();
        #pragma unroll
        for (int s = 0; s < 16; s++)
            hr[s][t] = g_h1[((size_t)(b << 12) + nb + s) * 256 + t];
        if (t < 16) al[t] = g_alpha[(b << 12) + nb + t];
        __syncthreads();
        float sacc[16];
        #pragma unroll
        for (int r = 0; r < 16; r++) sacc[r] = bfc;
        #pragma unroll 4
        for (int d = 0; d < 256; d += 4) {
            float w0 = Wf[(d + 0) * 512 + ch];
            float w1 = Wf[(d + 1) * 512 + ch];
            float w2 = Wf[(d + 2) * 512 + ch];
            float w3 = Wf[(d + 3) * 512 + ch];
            #pragma unroll
            for (int r = 0; r < 16; r++) {
                float4 hv = *(const float4*)&hr[r][d];
                sacc[r] = fmaf(hv.x, w0, fmaf(hv.y, w1, fmaf(hv.z, w2, fmaf(hv.w, w3, sacc[r]))));
            }
        }
        #pragma unroll
        for (int r = 0; r < 16; r++) {
            float f = sacc[r] > 0.f ? sacc[r] : 0.f;
            acc = fmaf(al[r], f, acc);
        }
    }
    g_pool[((slab << 2) + b) * 512 + ch] = acc;
}

__global__ void poolred_k() {
    int gid = blockIdx.x * 256 + threadIdx.x;  // BB*512
    if (gid >= BB * 512) return;
    int b = gid >> 9, ch = gid & 511;
    float s = 0.f;
    for (int sl = 0; sl < 32; sl++) s += g_pool[((sl << 2) + b) * 512 + ch];
    g_pooled[gid] = s;
}

__global__ void final_k(const float* __restrict__ Wl, const float* __restrict__ bl,
                        float* __restrict__ out) {
    int b = blockIdx.x, o = threadIdx.x;
    const float* p = g_pooled + b * 512;
    float s = bl[o];
    #pragma unroll 8
    for (int f = 0; f < 512; f++) s = fmaf(p[f], Wl[f * 256 + o], s);
    out[b * 256 + o] = s;
}

// ---------------- launch ------------------------------------------------------
extern "C" void kernel_launch(void* const* d_in, const int* in_sizes, int n_in,
                              void* d_out, int out_size) {
    (void)in_sizes; (void)n_in; (void)out_size;
    const float* x   = (const float*)d_in[0];
    const float* Wt0 = (const float*)d_in[1];
    const float* Wp0 = (const float*)d_in[3];
    const float* g0  = (const float*)d_in[5];
    const float* be0 = (const float*)d_in[6];
    const float* Wt1 = (const float*)d_in[7];
    const float* Wp1 = (const float*)d_in[9];
    const float* g1  = (const float*)d_in[11];
    const float* be1 = (const float*)d_in[12];
    const float* Wg  = (const float*)d_in[13];
    const float* bg  = (const float*)d_in[14];
    const float* Wf  = (const float*)d_in[15];
    const float* bf  = (const float*)d_in[16];
    const float* Wl  = (const float*)d_in[17];
    const float* bl  = (const float*)d_in[18];
    float* out = (float*)d_out;

    // ---- layer 0 ----
    prep_k<<<65, 256>>>(Wt0, Wp0, Wt1, Wp1);
    norms3_k<<<64, 256>>>(x);
    uv0_k<<<NPTS * 64 / 256, 256>>>(x, Wt0);
    knn0_k<<<NPTS, 256>>>(x);
    gather_k<64><<<STATS_BLOCKS, 256>>>();
    fin_k<64><<<1, 64>>>(g0, be0);
    finish_k<64><<<NPTS * 64 / 256, 256>>>();

    // ---- layer 1 ----
    norms64_k<<<NPTS * 32 / 256, 256>>>();
    gemm16_k<<<NPTS / 16, 256>>>(Wt1);               // u1 & v1 fused
    dist_gemm_k<<<dim3(2080, BB), 256>>>();
    knn1_k<<<NPTS, 256>>>();
    gather_k<256><<<STATS_BLOCKS, 256>>>();
    fin_k<256><<<1, 256>>>(g1, be1);
    finish_k<256><<<NPTS * 256 / 256, 256>>>();

    // ---- attention pooling + final linear ----
    gate_k<<<NPTS * 32 / 256, 256>>>(Wg, bg);
    softmax_k<<<BB, 256>>>();
    pool_k<<<dim3(BB, 2, 32), 256>>>(Wf, bf);
    poolred_k<<<8, 256>>>();
    final_k<<<BB, 256>>>(Wl, bl, out);
}